// round 17
// baseline (speedup 1.0000x reference)
#include <cuda_runtime.h>
#include <cstdint>

#define ROW_LEN   16384
#define KSEL      64
#define MAXROWS   8192
#define UNITS_PER_ROW 16          // 2 CTAs/row x 8 warps
#define SEG       48              // candidate slots per warp-unit
#define T0F       2.30f           // filter threshold; exact fallback covers any input
#define DCAP      256             // dense candidate capacity (8 regs/lane)
#define DREG      8

// Global scratch (static — no allocations).
__device__ uint32_t g_cnt[MAXROWS * UNITS_PER_ROW];
__device__ uint32_t g_seg[MAXROWS * UNITS_PER_ROW * SEG];   // ~25 MB (L2-resident)
__device__ uint32_t g_done[MAXROWS];                        // zero-init; self-resetting

// Monotonic transform: descending float order == descending uint order.
__device__ __forceinline__ uint32_t fwd_xform(uint32_t u) {
    return (u & 0x80000000u) ? ~u : (u | 0x80000000u);
}
__device__ __forceinline__ float inv_xform(uint32_t u) {
    return __uint_as_float((u & 0x80000000u) ? (u ^ 0x80000000u) : ~u);
}

// ---------------------------------------------------------------------------
// Fused kernel. Streaming filter is the proven warp-independent ballot-scan
// body (byte-identical hot path). After each warp's pushes, a per-warp
// handshake elects the 16th (last) warp of each row as the selector; it runs
// the proven warp-scoped exact select inline. No block barriers anywhere.
// ---------------------------------------------------------------------------
__global__ void __launch_bounds__(256, 5)
topk_fused_kernel(const float* __restrict__ x, float* __restrict__ out) {
    __shared__ uint32_t dense[DCAP];
    __shared__ uint32_t selbuf[KSEL];
    __shared__ uint32_t fcnt;

    const int cta  = blockIdx.x;
    const int row  = cta >> 1;          // both CTAs of a pair share one row
    const int tid  = threadIdx.x;
    const int wid  = tid >> 5;
    const int lane = tid & 31;

    // ---- Phase 1: streaming filter (unchanged proven body) ----
    const uint32_t unit = (uint32_t)cta * 8 + wid;
    uint32_t* seg = g_seg + (size_t)unit * SEG;
    const uint32_t lmask = (1u << lane) - 1u;

    const float4* src4 = reinterpret_cast<const float4*>(x)
                       + (size_t)cta * 2048 + wid * 256 + lane;

    float4 v[8];
    #pragma unroll
    for (int j = 0; j < 8; ++j)
        v[j] = __ldcs(&src4[j * 32]);

    uint32_t cnt = 0;
    #pragma unroll
    for (int j = 0; j < 8; ++j) {
        float f[4] = {v[j].x, v[j].y, v[j].z, v[j].w};
        #pragma unroll
        for (int c = 0; c < 4; ++c) {
            bool p = f[c] > T0F;
            unsigned m = __ballot_sync(0xFFFFFFFFu, p);
            uint32_t pos = cnt + (uint32_t)__popc(m & lmask);
            if (p && pos < SEG) seg[pos] = __float_as_uint(f[c]);
            cnt += (uint32_t)__popc(m);
        }
    }
    if (lane == 0) g_cnt[unit] = cnt;   // cnt > SEG routes selector to fallback

    // ---- Handshake: last of the row's 16 warps becomes the selector ----
    __threadfence();                     // release: seg/cnt visible before arrive
    uint32_t old = 0;
    if (lane == 0) old = atomicAdd(&g_done[row], 1u);
    old = __shfl_sync(0xFFFFFFFFu, old, 0);
    if (old != UNITS_PER_ROW - 1) return;   // 15 warps retire immediately

    if (lane == 0) g_done[row] = 0u;     // reset for next graph replay
    __threadfence();                     // acquire: see all 16 units' data

    // ---- Phase 2: warp-scoped exact select (proven round-16 body) ----
    uint32_t myc = (lane < UNITS_PER_ROW) ? g_cnt[row * UNITS_PER_ROW + lane] : 0u;
    const uint32_t total = __reduce_add_sync(0xFFFFFFFFu, myc);
    const bool ovf = __any_sync(0xFFFFFFFFu, myc > SEG);
    const bool fb  = ovf || (total < KSEL) || (total > DCAP);

    uint32_t T;          // transformed bit pattern of the 64th largest
    uint32_t total_gt;   // # strictly greater than T (<= 63)

    if (!fb) {
        // Exclusive prefix of unit counts (lanes >=16 contribute 0).
        uint32_t off = myc;
        #pragma unroll
        for (int d = 1; d < 32; d <<= 1) {
            uint32_t vv = __shfl_up_sync(0xFFFFFFFFu, off, d);
            if (lane >= d) off += vv;
        }
        const uint32_t excl_me = off - myc;

        // Compact into dense[0..total) (2 lanes per unit).
        const int gunit = lane >> 1;
        const int sub   = lane & 1;
        const uint32_t cu   = __shfl_sync(0xFFFFFFFFu, myc, gunit);
        const uint32_t base = __shfl_sync(0xFFFFFFFFu, excl_me, gunit);
        const uint32_t* segp = g_seg + ((size_t)row * UNITS_PER_ROW + gunit) * SEG;

        uint32_t land = 0xFFFFFFFFu, lor = 0;  // AND/OR over real candidates
        for (uint32_t j = sub; j < cu; j += 2) {
            uint32_t w = segp[j] | 0x80000000u;   // transformed (all positive)
            dense[base + j] = w;
            land &= w; lor |= w;
        }
        const uint32_t and_all = __reduce_and_sync(0xFFFFFFFFu, land);
        const uint32_t or_all  = __reduce_or_sync(0xFFFFFFFFu, lor);
        __syncwarp();

        uint32_t t[DREG];
        #pragma unroll
        for (int r = 0; r < DREG; ++r) {
            const uint32_t idx = (uint32_t)lane + 32u * r;
            t[r] = (idx < total) ? dense[idx] : 0u;
        }

        // Bitwise search, skipping the common prefix, with exact-count early
        // exit: when #{x >= c} == KSEL, the KSEL-th largest is min{x >= c}.
        const uint32_t diff = and_all ^ or_all;
        if (diff == 0) {
            T = and_all;
        } else {
            const int hb = 31 - __clz(diff);
            T = (hb == 31) ? 0u : (and_all & ~((2u << hb) - 1u));
            #pragma unroll 1
            for (int b = hb; b >= 0; --b) {
                const uint32_t c = T | (1u << b);
                int loc = 0;
                #pragma unroll
                for (int r = 0; r < DREG; ++r) loc += (int)(t[r] >= c);
                const int n = __reduce_add_sync(0xFFFFFFFFu, loc);
                if (n >= KSEL) T = c;
                if (n == KSEL) {   // warp-uniform: exact hit, finish with min
                    uint32_t mn = 0xFFFFFFFFu;
                    #pragma unroll
                    for (int r = 0; r < DREG; ++r)
                        if (t[r] >= c) mn = min(mn, t[r]);
                    T = __reduce_min_sync(0xFFFFFFFFu, mn);
                    break;
                }
            }
        }

        // Compact strict survivors via shfl exclusive scan.
        int cg = 0;
        #pragma unroll
        for (int r = 0; r < DREG; ++r) cg += (int)(t[r] > T);
        int so = cg;
        #pragma unroll
        for (int d = 1; d < 32; d <<= 1) {
            int vv = __shfl_up_sync(0xFFFFFFFFu, so, d);
            if (lane >= d) so += vv;
        }
        total_gt = (uint32_t)__shfl_sync(0xFFFFFFFFu, so, 31);
        so -= cg;  // exclusive
        #pragma unroll
        for (int r = 0; r < DREG; ++r)
            if (t[r] > T) selbuf[so++] = t[r];
        __syncwarp();
    } else {
        // Exact fallback over the full row (any input distribution).
        const uint32_t* src = reinterpret_cast<const uint32_t*>(x) + (size_t)row * ROW_LEN;
        T = 0;
        #pragma unroll 1
        for (int b = 31; b >= 0; --b) {
            const uint32_t c = T | (1u << b);
            int loc = 0;
            for (int i = lane; i < ROW_LEN; i += 32)
                loc += (int)(fwd_xform(src[i]) >= c);
            if (__reduce_add_sync(0xFFFFFFFFu, loc) >= KSEL) T = c;
        }
        if (lane == 0) fcnt = 0;
        __syncwarp();
        for (int i = lane; i < ROW_LEN; i += 32) {
            uint32_t u = fwd_xform(src[i]);
            if (u > T) selbuf[atomicAdd(&fcnt, 1u)] = u;  // < 64 by construction
        }
        __syncwarp();
        total_gt = fcnt;
    }

    // ---- Register tie-fill + descending bitonic sort of 64 (2 regs/lane) ----
    uint32_t a = ((uint32_t)lane      < total_gt) ? selbuf[lane]      : T;
    uint32_t b = ((uint32_t)lane + 32 < total_gt) ? selbuf[lane + 32] : T;

    #pragma unroll
    for (int k = 2; k <= 64; k <<= 1) {
        #pragma unroll
        for (int j = k >> 1; j > 0; j >>= 1) {
            if (j == 32) {
                uint32_t mx = a > b ? a : b;
                uint32_t mn = a > b ? b : a;
                a = mx; b = mn;
            } else {
                {
                    const int i = lane;
                    uint32_t p = __shfl_xor_sync(0xFFFFFFFFu, a, j);
                    bool keep_max = ((i & j) == 0) ^ ((i & k) != 0);
                    a = keep_max ? (a > p ? a : p) : (a < p ? a : p);
                }
                {
                    const int i = lane + 32;
                    uint32_t p = __shfl_xor_sync(0xFFFFFFFFu, b, j);
                    bool keep_max = ((i & j) == 0) ^ ((i & k) != 0);
                    b = keep_max ? (b > p ? b : p) : (b < p ? b : p);
                }
            }
        }
    }

    out[(size_t)row * KSEL + lane]      = inv_xform(a);
    out[(size_t)row * KSEL + lane + 32] = inv_xform(b);
}

extern "C" void kernel_launch(void* const* d_in, const int* in_sizes, int n_in,
                              void* d_out, int out_size) {
    const float* x = (const float*)d_in[0];
    float* out = (float*)d_out;
    int rows = in_sizes[0] / ROW_LEN;
    if (rows > MAXROWS) rows = MAXROWS;
    topk_fused_kernel<<<rows * 2, 256>>>(x, out);
}